// round 5
// baseline (speedup 1.0000x reference)
#include <cuda_runtime.h>
#include <cuda_fp16.h>

#define NCODES 4096
#define DIM 64
#define NPTS 65536          // B*S
#define NTIL 32             // code tiles of 128
#define TILE_BYTES 16896    // 16384 fp16 B-frags + 512 csq(f32)
#define DECAY_F 0.99f
#define OMD_F 0.01f
#define EPS_F 1e-5f

// ---------------- device scratch (no allocations allowed) ----------------
__device__ float g_counts[NCODES];
__device__ float g_embed[NCODES * DIM];
__device__ float g_ncs[NCODES];
__device__ float g_factor[NCODES];
// Codebook as fp16 in m16n8k16 B-fragment order, csq(f32) appended per tile.
__device__ __align__(16) unsigned char g_cbB[NTIL * TILE_BYTES];

// ---------------- smem layout (bytes) ----------------
#define OFF_APK  0            // A frag pack: [ks4][mt8][lane32] uint4 = 16 KB
#define OFF_B    16384        // 2 x 16896 (B frags + csq)
#define OFF_CAND 50176        // 128 pts x 8 cand ints = 4 KB
#define SMEM_TOTAL 54272

static __device__ __forceinline__ void mma16(float* c, const uint4& a,
                                             unsigned b0, unsigned b1) {
    asm("mma.sync.aligned.m16n8k16.row.col.f32.f16.f16.f32 "
        "{%0,%1,%2,%3}, {%4,%5,%6,%7}, {%8,%9}, {%0,%1,%2,%3};"
        : "+f"(c[0]), "+f"(c[1]), "+f"(c[2]), "+f"(c[3])
        : "r"(a.x), "r"(a.y), "r"(a.z), "r"(a.w), "r"(b0), "r"(b1));
}
static __device__ __forceinline__ void cp16(unsigned dst, const void* src) {
    asm volatile("cp.async.cg.shared.global [%0], [%1], 16;" :: "r"(dst), "l"(src));
}
#define CP_COMMIT() asm volatile("cp.async.commit_group;" ::: "memory")
#define CP_WAIT1()  asm volatile("cp.async.wait_group 1;" ::: "memory")

// sorted ascending top-4 insert, constant-indexed
#define TOP4_INS(s, v, ix)                                                  \
    if ((v) < td##s[3]) {                                                   \
        if ((v) < td##s[2]) {                                               \
            td##s[3] = td##s[2]; ti##s[3] = ti##s[2];                       \
            if ((v) < td##s[1]) {                                           \
                td##s[2] = td##s[1]; ti##s[2] = ti##s[1];                   \
                if ((v) < td##s[0]) {                                       \
                    td##s[1] = td##s[0]; ti##s[1] = ti##s[0];               \
                    td##s[0] = (v); ti##s[0] = (ix);                        \
                } else { td##s[1] = (v); ti##s[1] = (ix); }                 \
            } else { td##s[2] = (v); ti##s[2] = (ix); }                     \
        } else { td##s[3] = (v); ti##s[3] = (ix); }                         \
    }

// ---- prep: codebook -> fp16 B-frag layout + csq; zero scratch ----
__global__ void prep_kernel(const float* __restrict__ codebook) {
    int i = blockIdx.x * blockDim.x + threadIdx.x;  // 0..262143
    if (i >= NCODES * DIM) return;
    int k = i >> 6, d = i & 63;
    float v = codebook[i];
    int tile = k >> 7, nloc = k & 127, nt = nloc >> 3, nn = nloc & 7;
    int ks = d >> 4, c = d & 15;
    int lane = nn * 4 + ((c & 7) >> 1);
    unsigned off = (unsigned)tile * TILE_BYTES +
                   (((ks * 8 + (nt >> 1)) * 32 + lane) * 16) +
                   (nt & 1) * 8 + (c >> 3) * 4 + (c & 1) * 2;
    *(__half*)(g_cbB + off) = __float2half_rn(v);
    g_embed[i] = 0.0f;
    if (d == 0) {
        g_counts[k] = 0.0f;
        const float* row = codebook + (size_t)k * DIM;
        float s = 0.0f;
#pragma unroll
        for (int j = 0; j < DIM; j++) s += row[j] * row[j];
        *(float*)(g_cbB + (unsigned)tile * TILE_BYTES + 16384 + nloc * 4) = s;
    }
}

// ---- main: fp16 1-pass mma GEMM + top-4 select + exact refine + EMA ----
__global__ void __launch_bounds__(256, 1) vq_kernel(
    const float* __restrict__ x, const float* __restrict__ codebook,
    float* __restrict__ o_quant, float* __restrict__ o_idx) {
    extern __shared__ char smem[];
    const int tid = threadIdx.x;
    const int lane = tid & 31, w = tid >> 5;
    const int rw = w >> 1, cw = w & 1;  // row-warp(32 pts), col-warp(64 codes)

    // --- prologue: pack x tile (fp16) into A-fragment layout ---
    if (tid < 128) {
        const int m = tid;
        const int mt = m >> 4, mm = m & 15, rh = mm >> 3, gr = mm & 7;
        const float4* xr = (const float4*)(x + ((size_t)blockIdx.x * 128 + m) * DIM);
#pragma unroll
        for (int j = 0; j < 16; j++) {
            float4 v4 = xr[j];
            float vv[4] = {v4.x, v4.y, v4.z, v4.w};
#pragma unroll
            for (int e = 0; e < 4; e++) {
                int d = j * 4 + e;
                int ks = d >> 4, c = d & 15;
                int ln = gr * 4 + ((c & 7) >> 1);
                int reg = (c >> 3) * 2 + rh;
                unsigned off = (((ks * 8 + mt) * 32 + ln) * 16) + reg * 4 + (c & 1) * 2;
                *(__half*)(smem + OFF_APK + off) = __float2half_rn(vv[e]);
            }
        }
    }

    // --- prefetch B tiles 0,1 ---
    const unsigned smem_b = (unsigned)__cvta_generic_to_shared(smem + OFF_B);
#pragma unroll
    for (int t = 0; t < 2; t++) {
        const unsigned char* src = g_cbB + (size_t)t * TILE_BYTES;
        for (int c = tid; c < TILE_BYTES / 16; c += 256)
            cp16(smem_b + t * TILE_BYTES + c * 16, src + c * 16);
        CP_COMMIT();
    }
    __syncthreads();

    // --- load A frags into registers ---
    uint4 afr[4][2];
    {
        const uint4* A4 = (const uint4*)(smem + OFF_APK);
#pragma unroll
        for (int ks = 0; ks < 4; ks++)
#pragma unroll
            for (int mt2 = 0; mt2 < 2; mt2++)
                afr[ks][mt2] = A4[(ks * 8 + rw * 2 + mt2) * 32 + lane];
    }

    // per-lane top-4 state, slot = mt2*2+rh
    float td0[4] = {3.4e38f, 3.4e38f, 3.4e38f, 3.4e38f}; int ti0[4] = {0, 0, 0, 0};
    float td1[4] = {3.4e38f, 3.4e38f, 3.4e38f, 3.4e38f}; int ti1[4] = {0, 0, 0, 0};
    float td2[4] = {3.4e38f, 3.4e38f, 3.4e38f, 3.4e38f}; int ti2[4] = {0, 0, 0, 0};
    float td3[4] = {3.4e38f, 3.4e38f, 3.4e38f, 3.4e38f}; int ti3[4] = {0, 0, 0, 0};

    for (int t = 0; t < NTIL; ++t) {
        const int buf = t & 1;
        CP_WAIT1();
        __syncthreads();

        float acc[64];
#pragma unroll
        for (int i = 0; i < 64; i++) acc[i] = 0.0f;

        const uint4* B4 = (const uint4*)(smem + OFF_B + buf * TILE_BYTES);
#pragma unroll
        for (int ks = 0; ks < 4; ks++)
#pragma unroll
            for (int ntp = 0; ntp < 4; ntp++) {
                uint4 b = B4[(ks * 8 + cw * 4 + ntp) * 32 + lane];
#pragma unroll
                for (int mt2 = 0; mt2 < 2; mt2++) {
                    mma16(&acc[(mt2 * 8 + ntp * 2 + 0) * 4], afr[ks][mt2], b.x, b.y);
                    mma16(&acc[(mt2 * 8 + ntp * 2 + 1) * 4], afr[ks][mt2], b.z, b.w);
                }
            }

        // --- selection epilogue: s = csq - 2*dot, top-4 per slot ---
        const float* csqS = (const float*)(smem + OFF_B + buf * TILE_BYTES + 16384);
        float csqr[16];
#pragma unroll
        for (int nt = 0; nt < 8; nt++)
#pragma unroll
            for (int h = 0; h < 2; h++)
                csqr[nt * 2 + h] = csqS[cw * 64 + nt * 8 + 2 * (lane & 3) + h];

        const int kb = t * 128 + cw * 64 + 2 * (lane & 3);
#pragma unroll
        for (int nt = 0; nt < 8; nt++)
#pragma unroll
            for (int h = 0; h < 2; h++) {
                const int ix = kb + nt * 8 + h;
                const float cq = csqr[nt * 2 + h];
                float s0 = fmaf(-2.0f, acc[(0 * 8 + nt) * 4 + 0 + h], cq);
                float s1 = fmaf(-2.0f, acc[(0 * 8 + nt) * 4 + 2 + h], cq);
                float s2 = fmaf(-2.0f, acc[(1 * 8 + nt) * 4 + 0 + h], cq);
                float s3 = fmaf(-2.0f, acc[(1 * 8 + nt) * 4 + 2 + h], cq);
                TOP4_INS(0, s0, ix);
                TOP4_INS(1, s1, ix);
                TOP4_INS(2, s2, ix);
                TOP4_INS(3, s3, ix);
            }

        __syncthreads();
        if (t + 2 < NTIL) {
            const unsigned char* src = g_cbB + (size_t)(t + 2) * TILE_BYTES;
            for (int c = tid; c < TILE_BYTES / 16; c += 256)
                cp16(smem_b + buf * TILE_BYTES + c * 16, src + c * 16);
        }
        CP_COMMIT();
    }

    // --- merge top-4 across the 4 lanes sharing each point row ---
#pragma unroll
    for (int off = 1; off <= 2; off <<= 1) {
#pragma unroll
        for (int r = 0; r < 4; r++) {
            float v; int ix;
            v = __shfl_xor_sync(0xffffffffu, td0[r], off);
            ix = __shfl_xor_sync(0xffffffffu, ti0[r], off);
            TOP4_INS(0, v, ix);
            v = __shfl_xor_sync(0xffffffffu, td1[r], off);
            ix = __shfl_xor_sync(0xffffffffu, ti1[r], off);
            TOP4_INS(1, v, ix);
            v = __shfl_xor_sync(0xffffffffu, td2[r], off);
            ix = __shfl_xor_sync(0xffffffffu, ti2[r], off);
            TOP4_INS(2, v, ix);
            v = __shfl_xor_sync(0xffffffffu, td3[r], off);
            ix = __shfl_xor_sync(0xffffffffu, ti3[r], off);
            TOP4_INS(3, v, ix);
        }
    }

    int* candS = (int*)(smem + OFF_CAND);
    if ((lane & 3) == 0) {
        const int pr = lane >> 2;
#pragma unroll
        for (int r = 0; r < 4; r++) {
            candS[(rw * 32 + 0 * 16 + 0 * 8 + pr) * 8 + cw * 4 + r] = ti0[r];
            candS[(rw * 32 + 0 * 16 + 1 * 8 + pr) * 8 + cw * 4 + r] = ti1[r];
            candS[(rw * 32 + 1 * 16 + 0 * 8 + pr) * 8 + cw * 4 + r] = ti2[r];
            candS[(rw * 32 + 1 * 16 + 1 * 8 + pr) * 8 + cw * 4 + r] = ti3[r];
        }
    }
    __syncthreads();

    // --- exact fp32 refine: warp per point, 8 candidates x 4 lanes each ---
    const int cd = lane >> 2, sub = lane & 3;
    for (int ii = 0; ii < 16; ii++) {
        const int pt = w * 16 + ii;
        const int gpt = blockIdx.x * 128 + pt;
        const int cidx = candS[pt * 8 + cd];

        const float4* xr = (const float4*)(x + (size_t)gpt * DIM) + sub * 4;
        const float4* cr = (const float4*)(codebook + (size_t)cidx * DIM) + sub * 4;
        float dot = 0.0f, xsq = 0.0f, csq = 0.0f;
#pragma unroll
        for (int j = 0; j < 4; j++) {
            float4 xa = xr[j], ca = cr[j];
            dot = fmaf(xa.x, ca.x, dot); xsq = fmaf(xa.x, xa.x, xsq); csq = fmaf(ca.x, ca.x, csq);
            dot = fmaf(xa.y, ca.y, dot); xsq = fmaf(xa.y, xa.y, xsq); csq = fmaf(ca.y, ca.y, csq);
            dot = fmaf(xa.z, ca.z, dot); xsq = fmaf(xa.z, xa.z, xsq); csq = fmaf(ca.z, ca.z, csq);
            dot = fmaf(xa.w, ca.w, dot); xsq = fmaf(xa.w, xa.w, xsq); csq = fmaf(ca.w, ca.w, csq);
        }
#pragma unroll
        for (int o = 1; o <= 2; o <<= 1) {
            dot += __shfl_xor_sync(0xffffffffu, dot, o);
            xsq += __shfl_xor_sync(0xffffffffu, xsq, o);
            csq += __shfl_xor_sync(0xffffffffu, csq, o);
        }
        float d = fmaf(-2.0f, dot, xsq) + csq;
        int wi = cidx;
#pragma unroll
        for (int o = 4; o <= 16; o <<= 1) {
            float od = __shfl_xor_sync(0xffffffffu, d, o);
            int oi = __shfl_xor_sync(0xffffffffu, wi, o);
            if (od < d || (od == d && oi < wi)) { d = od; wi = oi; }
        }

        if (lane == 0) o_idx[gpt] = (float)wi;
        ((float2*)(o_quant + (size_t)gpt * DIM))[lane] =
            ((const float2*)(codebook + (size_t)wi * DIM))[lane];
        if (lane == 0) atomicAdd(&g_counts[wi], 1.0f);
        float2 xv2 = ((const float2*)(x + (size_t)gpt * DIM))[lane];
        atomicAdd(&g_embed[(size_t)wi * DIM + 2 * lane], xv2.x);
        atomicAdd(&g_embed[(size_t)wi * DIM + 2 * lane + 1], xv2.y);
    }
}

// ---- finalize 1: new_cluster_size, n, smoothing reciprocal ----
__global__ void finalize1_kernel(const float* __restrict__ cluster_size,
                                 float* __restrict__ o_cs) {
    __shared__ float warpsum[32];
    __shared__ float s_n;
    float local = 0.0f;
    for (int k = threadIdx.x; k < NCODES; k += blockDim.x) {
        float ncs = DECAY_F * cluster_size[k] + OMD_F * g_counts[k];
        o_cs[k] = ncs;
        g_ncs[k] = ncs;
        local += ncs;
    }
#pragma unroll
    for (int o = 16; o; o >>= 1) local += __shfl_down_sync(0xffffffffu, local, o);
    if ((threadIdx.x & 31) == 0) warpsum[threadIdx.x >> 5] = local;
    __syncthreads();
    if (threadIdx.x < 32) {
        float v = (threadIdx.x < (blockDim.x >> 5)) ? warpsum[threadIdx.x] : 0.0f;
#pragma unroll
        for (int o = 16; o; o >>= 1) v += __shfl_down_sync(0xffffffffu, v, o);
        if (threadIdx.x == 0) s_n = v;
    }
    __syncthreads();
    float n = s_n;
    float denom = n + (float)NCODES * EPS_F;
    for (int k = threadIdx.x; k < NCODES; k += blockDim.x) {
        float sm = (g_ncs[k] + EPS_F) / denom * n;
        g_factor[k] = 1.0f / sm;
    }
}

// ---- finalize 2: new_ema_w, new_codebook ----
__global__ void finalize2_kernel(const float* __restrict__ ema_w,
                                 float* __restrict__ o_cb,
                                 float* __restrict__ o_ema) {
    int i = blockIdx.x * blockDim.x + threadIdx.x;
    if (i >= NCODES * DIM) return;
    float e = DECAY_F * ema_w[i] + OMD_F * g_embed[i];
    o_ema[i] = e;
    o_cb[i] = e * g_factor[i >> 6];
}

extern "C" void kernel_launch(void* const* d_in, const int* in_sizes, int n_in,
                              void* d_out, int out_size) {
    const float* x            = (const float*)d_in[0];
    const float* codebook     = (const float*)d_in[1];
    const float* cluster_size = (const float*)d_in[2];
    const float* ema_w        = (const float*)d_in[3];

    float* out     = (float*)d_out;
    float* o_quant = out;                           // 16*4096*64
    float* o_idx   = o_quant + (size_t)NPTS * DIM;  // 16*4096
    float* o_cb    = o_idx + NPTS;                  // 4096*64
    float* o_cs    = o_cb + (size_t)NCODES * DIM;   // 4096
    float* o_ema   = o_cs + NCODES;                 // 4096*64

    static int smem_set = 0;
    if (!smem_set) {
        cudaFuncSetAttribute(vq_kernel, cudaFuncAttributeMaxDynamicSharedMemorySize, SMEM_TOTAL);
        smem_set = 1;
    }

    prep_kernel<<<(NCODES * DIM + 255) / 256, 256>>>(codebook);
    vq_kernel<<<NPTS / 128, 256, SMEM_TOTAL>>>(x, codebook, o_quant, o_idx);
    finalize1_kernel<<<1, 1024>>>(cluster_size, o_cs);
    finalize2_kernel<<<(NCODES * DIM + 255) / 256, 256>>>(ema_w, o_cb, o_ema);
}

// round 6
// speedup vs baseline: 1.7835x; 1.7835x over previous
#include <cuda_runtime.h>
#include <cuda_fp16.h>

#define NCODES 4096
#define DIM 64
#define NPTS 65536
#define NTIL 32
#define TILE_B 20480        // 128 codes x 80 k x fp16
#define MARGIN 2.0f
#define DECAY_F 0.99f
#define OMD_F 0.01f
#define EPS_F 1e-5f

__device__ float g_counts[NCODES];
__device__ float g_embed[NCODES * DIM];
__device__ float g_ncs[NCODES];
__device__ float g_factor[NCODES];
__device__ float g_csq[NCODES];
__device__ __align__(16) unsigned char g_cbB[NTIL * TILE_B];

#define OFF_B    0            // 2 x 20480
#define OFF_TM   40960        // [w8][slot2][r8][t32][c4] u32 = 64 KB
#define OFF_PMIN 106496       // 128 f32
#define SMEM_TOTAL 107008

static __device__ __forceinline__ unsigned hmin2u(unsigned a, unsigned b) {
    __half2 r = __hmin2(*(__half2*)&a, *(__half2*)&b);
    return *(unsigned*)&r;
}
static __device__ __forceinline__ unsigned packh2(float lo, float hi) {
    __half2 h = __floats2half2_rn(lo, hi);
    return *(unsigned*)&h;
}
static __device__ __forceinline__ float h2lo(unsigned u) { return __low2float(*(__half2*)&u); }
static __device__ __forceinline__ float h2hi(unsigned u) { return __high2float(*(__half2*)&u); }

static __device__ __forceinline__ void mmaA(unsigned& d0, unsigned& d1,
                                            const unsigned* a, unsigned b0, unsigned b1) {
    asm("mma.sync.aligned.m16n8k16.row.col.f16.f16.f16.f16 "
        "{%0,%1}, {%2,%3,%4,%5}, {%6,%7}, {%0,%1};"
        : "+r"(d0), "+r"(d1)
        : "r"(a[0]), "r"(a[1]), "r"(a[2]), "r"(a[3]), "r"(b0), "r"(b1));
}
static __device__ __forceinline__ void mmaZ(unsigned& d0, unsigned& d1,
                                            const unsigned* a, unsigned b0, unsigned b1) {
    asm("mma.sync.aligned.m16n8k16.row.col.f16.f16.f16.f16 "
        "{%0,%1}, {%2,%3,%4,%5}, {%6,%7}, {%8,%8};"
        : "=r"(d0), "=r"(d1)
        : "r"(a[0]), "r"(a[1]), "r"(a[2]), "r"(a[3]), "r"(b0), "r"(b1), "r"(0u));
}
static __device__ __forceinline__ void cp16(unsigned dst, const void* src) {
    asm volatile("cp.async.cg.shared.global [%0], [%1], 16;" :: "r"(dst), "l"(src));
}
#define CP_COMMIT() asm volatile("cp.async.commit_group;" ::: "memory")
#define CP_WAIT1()  asm volatile("cp.async.wait_group 1;" ::: "memory")

// B-fragment offset (layout verified in R4), ks 0..4
static __device__ __forceinline__ unsigned bfrag_off(int tile, int n, int ks, int c) {
    int nt = n >> 3, nn = n & 7;
    return (unsigned)tile * TILE_B +
           (((ks * 8 + (nt >> 1)) * 32 + (nn * 4 + ((c & 7) >> 1))) * 16) +
           (nt & 1) * 8 + (c >> 3) * 4 + (c & 1) * 2;
}

// ---- prep: B frags = fp16(-2c); aug k-step = csq hi/lo; csq; zero scratch ----
__global__ void prep_kernel(const float* __restrict__ codebook) {
    int i = blockIdx.x * blockDim.x + threadIdx.x;
    if (i >= NCODES * DIM) return;
    int k = i >> 6, d = i & 63;
    int tile = k >> 7, n = k & 127;
    *(__half*)(g_cbB + bfrag_off(tile, n, d >> 4, d & 15)) =
        __float2half_rn(-2.0f * codebook[i]);
    g_embed[i] = 0.0f;
    if (d < 16) {
        __half av = __float2half_rn(0.0f);
        if (d < 2) {
            const float* row = codebook + (size_t)k * DIM;
            float s = 0.0f;
#pragma unroll
            for (int j = 0; j < DIM; j++) s += row[j] * row[j];
            if (d == 0) {
                g_csq[k] = s;
                g_counts[k] = 0.0f;
                av = __float2half_rn(s);
            } else {
                av = __float2half_rn(s - __half2float(__float2half_rn(s)));
            }
        }
        *(__half*)(g_cbB + bfrag_off(tile, n, 4, d)) = av;
    }
}

// ---- main ----
__global__ void __launch_bounds__(256, 2) vq_kernel(
    const float* __restrict__ x, const float* __restrict__ codebook,
    float* __restrict__ o_quant, float* __restrict__ o_idx) {
    extern __shared__ char smem[];
    const int tid = threadIdx.x, lane = tid & 31, w = tid >> 5;
    const int r0 = lane >> 2, c4 = lane & 3;

    // A fragments from gmem: rows w*16+r0 and +8
    unsigned afr[5][4];
    {
        const float* xr0 = x + ((size_t)blockIdx.x * 128 + w * 16 + r0) * DIM;
        const float* xr1 = xr0 + 8 * DIM;
#pragma unroll
        for (int ks = 0; ks < 4; ks++) {
            float2 a = *(const float2*)(xr0 + ks * 16 + 2 * c4);
            float2 b = *(const float2*)(xr1 + ks * 16 + 2 * c4);
            float2 c = *(const float2*)(xr0 + ks * 16 + 8 + 2 * c4);
            float2 d = *(const float2*)(xr1 + ks * 16 + 8 + 2 * c4);
            afr[ks][0] = packh2(a.x, a.y);
            afr[ks][1] = packh2(b.x, b.y);
            afr[ks][2] = packh2(c.x, c.y);
            afr[ks][3] = packh2(d.x, d.y);
        }
        afr[4][0] = afr[4][1] = (c4 == 0) ? 0x3C003C00u : 0u;
        afr[4][2] = afr[4][3] = 0u;
    }

    const unsigned smem_b = (unsigned)__cvta_generic_to_shared(smem + OFF_B);
#pragma unroll
    for (int t = 0; t < 2; t++) {
        const unsigned char* src = g_cbB + (size_t)t * TILE_B;
        for (int c = tid; c < TILE_B / 16; c += 256)
            cp16(smem_b + t * TILE_B + c * 16, src + c * 16);
        CP_COMMIT();
    }

    unsigned g0 = 0x7BFF7BFFu, g1 = 0x7BFF7BFFu;
    unsigned* tm = (unsigned*)(smem + OFF_TM);

    for (int t = 0; t < NTIL; ++t) {
        const int buf = t & 1;
        CP_WAIT1();
        __syncthreads();

        unsigned a0[16], a1[16];
        const uint4* B4 = (const uint4*)(smem + OFF_B + buf * TILE_B);
#pragma unroll
        for (int p = 0; p < 8; p++) {  // aug k-step, zero-init: acc = csq
            uint4 b = B4[(4 * 8 + p) * 32 + lane];
            mmaZ(a0[2 * p], a1[2 * p], afr[4], b.x, b.y);
            mmaZ(a0[2 * p + 1], a1[2 * p + 1], afr[4], b.z, b.w);
        }
#pragma unroll
        for (int ks = 0; ks < 4; ks++)
#pragma unroll
            for (int p = 0; p < 8; p++) {
                uint4 b = B4[(ks * 8 + p) * 32 + lane];
                mmaA(a0[2 * p], a1[2 * p], afr[ks], b.x, b.y);
                mmaA(a0[2 * p + 1], a1[2 * p + 1], afr[ks], b.z, b.w);
            }

        // hmin2 trees -> per-tile subset mins
        unsigned t0, t1;
        {
            unsigned m[8];
#pragma unroll
            for (int j = 0; j < 8; j++) m[j] = hmin2u(a0[j], a0[j + 8]);
#pragma unroll
            for (int j = 0; j < 4; j++) m[j] = hmin2u(m[j], m[j + 4]);
            t0 = hmin2u(hmin2u(m[0], m[1]), hmin2u(m[2], m[3]));
#pragma unroll
            for (int j = 0; j < 8; j++) m[j] = hmin2u(a1[j], a1[j + 8]);
#pragma unroll
            for (int j = 0; j < 4; j++) m[j] = hmin2u(m[j], m[j + 4]);
            t1 = hmin2u(hmin2u(m[0], m[1]), hmin2u(m[2], m[3]));
        }
        g0 = hmin2u(g0, t0);
        g1 = hmin2u(g1, t1);
        tm[(((w * 2 + 0) * 8 + r0) * 32 + t) * 4 + c4] = t0;
        tm[(((w * 2 + 1) * 8 + r0) * 32 + t) * 4 + c4] = t1;

        __syncthreads();
        if (t + 2 < NTIL) {
            const unsigned char* src = g_cbB + (size_t)(t + 2) * TILE_B;
            for (int c = tid; c < TILE_B / 16; c += 256)
                cp16(smem_b + buf * TILE_B + c * 16, src + c * 16);
        }
        CP_COMMIT();
    }

    // noisy per-point min
    g0 = hmin2u(g0, __shfl_xor_sync(0xffffffffu, g0, 1));
    g0 = hmin2u(g0, __shfl_xor_sync(0xffffffffu, g0, 2));
    g1 = hmin2u(g1, __shfl_xor_sync(0xffffffffu, g1, 1));
    g1 = hmin2u(g1, __shfl_xor_sync(0xffffffffu, g1, 2));
    float* pminS = (float*)(smem + OFF_PMIN);
    if (c4 == 0) {
        pminS[w * 16 + r0] = fminf(h2lo(g0), h2hi(g0));
        pminS[w * 16 + 8 + r0] = fminf(h2lo(g1), h2hi(g1));
    }
    __syncwarp();

    // recovery + exact refine, warp per point (own warp's 16 points)
    const uint4* tm4 = (const uint4*)tm;
    for (int ii = 0; ii < 16; ii++) {
        const int slot = ii >> 3, r = ii & 7;
        const int pl = w * 16 + slot * 8 + r;
        const int gpt = blockIdx.x * 128 + pl;
        const float th = pminS[pl] + MARGIN;

        float2 xv2 = ((const float2*)(x + (size_t)gpt * DIM))[lane];
        float xsq = fmaf(xv2.x, xv2.x, xv2.y * xv2.y);
#pragma unroll
        for (int o = 1; o <= 16; o <<= 1) xsq += __shfl_xor_sync(0xffffffffu, xsq, o);

        uint4 e = tm4[((w * 2 + slot) * 8 + r) * 32 + lane];  // tile=lane, c4 0..3
        unsigned m8 = 0;
        if (h2lo(e.x) < th) m8 |= 1u;
        if (h2hi(e.x) < th) m8 |= 2u;
        if (h2lo(e.y) < th) m8 |= 4u;
        if (h2hi(e.y) < th) m8 |= 8u;
        if (h2lo(e.z) < th) m8 |= 16u;
        if (h2hi(e.z) < th) m8 |= 32u;
        if (h2lo(e.w) < th) m8 |= 64u;
        if (h2hi(e.w) < th) m8 |= 128u;

        float bd = 3.4e38f;
        int bi = 0x7FFFFFFF;
        unsigned hitb = __ballot_sync(0xffffffffu, m8 != 0);
        while (hitb) {
            const int src = __ffs(hitb) - 1;
            hitb &= hitb - 1;
            unsigned m = __shfl_sync(0xffffffffu, m8, src);
            for (int bit = 0; bit < 8; bit++) {
                if (!(m & (1u << bit))) continue;
                const int code = src * 128 + (lane >> 1) * 8 + (bit >> 1) * 2 + (bit & 1);
                const int part = lane & 1;
                const float4* xr = (const float4*)(x + (size_t)gpt * DIM) + part * 8;
                const float4* cr = (const float4*)(codebook + (size_t)code * DIM) + part * 8;
                float dot = 0.0f;
#pragma unroll
                for (int j = 0; j < 8; j++) {
                    float4 xa = xr[j], ca = cr[j];
                    dot = fmaf(xa.x, ca.x, dot);
                    dot = fmaf(xa.y, ca.y, dot);
                    dot = fmaf(xa.z, ca.z, dot);
                    dot = fmaf(xa.w, ca.w, dot);
                }
                dot += __shfl_xor_sync(0xffffffffu, dot, 1);
                float dd = fmaf(-2.0f, dot, xsq) + g_csq[code];
                int wi = code;
#pragma unroll
                for (int o = 2; o <= 16; o <<= 1) {
                    float od = __shfl_xor_sync(0xffffffffu, dd, o);
                    int oi = __shfl_xor_sync(0xffffffffu, wi, o);
                    if (od < dd || (od == dd && oi < wi)) { dd = od; wi = oi; }
                }
                if (dd < bd || (dd == bd && wi < bi)) { bd = dd; bi = wi; }
            }
        }

        if (lane == 0) o_idx[gpt] = (float)bi;
        ((float2*)(o_quant + (size_t)gpt * DIM))[lane] =
            ((const float2*)(codebook + (size_t)bi * DIM))[lane];
        if (lane == 0) atomicAdd(&g_counts[bi], 1.0f);
        atomicAdd(&g_embed[(size_t)bi * DIM + 2 * lane], xv2.x);
        atomicAdd(&g_embed[(size_t)bi * DIM + 2 * lane + 1], xv2.y);
    }
}

__global__ void finalize1_kernel(const float* __restrict__ cluster_size,
                                 float* __restrict__ o_cs) {
    __shared__ float warpsum[32];
    __shared__ float s_n;
    float local = 0.0f;
    for (int k = threadIdx.x; k < NCODES; k += blockDim.x) {
        float ncs = DECAY_F * cluster_size[k] + OMD_F * g_counts[k];
        o_cs[k] = ncs;
        g_ncs[k] = ncs;
        local += ncs;
    }
#pragma unroll
    for (int o = 16; o; o >>= 1) local += __shfl_down_sync(0xffffffffu, local, o);
    if ((threadIdx.x & 31) == 0) warpsum[threadIdx.x >> 5] = local;
    __syncthreads();
    if (threadIdx.x < 32) {
        float v = (threadIdx.x < (blockDim.x >> 5)) ? warpsum[threadIdx.x] : 0.0f;
#pragma unroll
        for (int o = 16; o; o >>= 1) v += __shfl_down_sync(0xffffffffu, v, o);
        if (threadIdx.x == 0) s_n = v;
    }
    __syncthreads();
    float n = s_n;
    float denom = n + (float)NCODES * EPS_F;
    for (int k = threadIdx.x; k < NCODES; k += blockDim.x) {
        float sm = (g_ncs[k] + EPS_F) / denom * n;
        g_factor[k] = 1.0f / sm;
    }
}

__global__ void finalize2_kernel(const float* __restrict__ ema_w,
                                 float* __restrict__ o_cb,
                                 float* __restrict__ o_ema) {
    int i = blockIdx.x * blockDim.x + threadIdx.x;
    if (i >= NCODES * DIM) return;
    float e = DECAY_F * ema_w[i] + OMD_F * g_embed[i];
    o_ema[i] = e;
    o_cb[i] = e * g_factor[i >> 6];
}

extern "C" void kernel_launch(void* const* d_in, const int* in_sizes, int n_in,
                              void* d_out, int out_size) {
    const float* x            = (const float*)d_in[0];
    const float* codebook     = (const float*)d_in[1];
    const float* cluster_size = (const float*)d_in[2];
    const float* ema_w        = (const float*)d_in[3];

    float* out     = (float*)d_out;
    float* o_quant = out;
    float* o_idx   = o_quant + (size_t)NPTS * DIM;
    float* o_cb    = o_idx + NPTS;
    float* o_cs    = o_cb + (size_t)NCODES * DIM;
    float* o_ema   = o_cs + NCODES;

    static int smem_set = 0;
    if (!smem_set) {
        cudaFuncSetAttribute(vq_kernel, cudaFuncAttributeMaxDynamicSharedMemorySize, SMEM_TOTAL);
        smem_set = 1;
    }

    prep_kernel<<<(NCODES * DIM + 255) / 256, 256>>>(codebook);
    vq_kernel<<<NPTS / 128, 256, SMEM_TOTAL>>>(x, codebook, o_quant, o_idx);
    finalize1_kernel<<<1, 1024>>>(cluster_size, o_cs);
    finalize2_kernel<<<(NCODES * DIM + 255) / 256, 256>>>(ema_w, o_cb, o_ema);
}

// round 7
// speedup vs baseline: 1.9514x; 1.0941x over previous
#include <cuda_runtime.h>
#include <cuda_fp16.h>

#define NCODES 4096
#define DIM 64
#define NPTS 65536
#define NTIL 32
#define TILE_B 16640        // 128 codes x 64 k x fp16 + 256B csq-h2
#define MARGIN 2.0f
#define DECAY_F 0.99f
#define OMD_F 0.01f
#define EPS_F 1e-5f

__device__ float g_counts[NCODES];
__device__ float g_embed[NCODES * DIM];
__device__ float g_ncs[NCODES];
__device__ float g_factor[NCODES];
__device__ float g_csq[NCODES];
__device__ __align__(16) unsigned char g_cbB[NTIL * TILE_B];

#define OFF_B    0             // 2 x 16640 = 33280
#define OFF_TM   33280         // [pt128][t 32 pad->33][c4] u32 = 67584
#define OFF_PMIN 100864        // 128 f32
#define SMEM_TOTAL 101376

static __device__ __forceinline__ unsigned hmin2u(unsigned a, unsigned b) {
    __half2 r = __hmin2(*(__half2*)&a, *(__half2*)&b);
    return *(unsigned*)&r;
}
static __device__ __forceinline__ unsigned hadd2u(unsigned a, unsigned b) {
    __half2 r = __hadd2(*(__half2*)&a, *(__half2*)&b);
    return *(unsigned*)&r;
}
static __device__ __forceinline__ unsigned packh2(float lo, float hi) {
    __half2 h = __floats2half2_rn(lo, hi);
    return *(unsigned*)&h;
}
static __device__ __forceinline__ float h2lo(unsigned u) { return __low2float(*(__half2*)&u); }
static __device__ __forceinline__ float h2hi(unsigned u) { return __high2float(*(__half2*)&u); }

static __device__ __forceinline__ void mmaA(unsigned& d0, unsigned& d1,
                                            const unsigned* a, unsigned b0, unsigned b1) {
    asm("mma.sync.aligned.m16n8k16.row.col.f16.f16.f16.f16 "
        "{%0,%1}, {%2,%3,%4,%5}, {%6,%7}, {%0,%1};"
        : "+r"(d0), "+r"(d1)
        : "r"(a[0]), "r"(a[1]), "r"(a[2]), "r"(a[3]), "r"(b0), "r"(b1));
}
static __device__ __forceinline__ void mmaZ(unsigned& d0, unsigned& d1,
                                            const unsigned* a, unsigned b0, unsigned b1) {
    asm("mma.sync.aligned.m16n8k16.row.col.f16.f16.f16.f16 "
        "{%0,%1}, {%2,%3,%4,%5}, {%6,%7}, {%8,%8};"
        : "=r"(d0), "=r"(d1)
        : "r"(a[0]), "r"(a[1]), "r"(a[2]), "r"(a[3]), "r"(b0), "r"(b1), "r"(0u));
}
static __device__ __forceinline__ void cp16(unsigned dst, const void* src) {
    asm volatile("cp.async.cg.shared.global [%0], [%1], 16;" :: "r"(dst), "l"(src));
}
#define CP_COMMIT() asm volatile("cp.async.commit_group;" ::: "memory")
#define CP_WAIT1()  asm volatile("cp.async.wait_group 1;" ::: "memory")

// B-fragment offset (layout validated R4/R6), ks 0..3
static __device__ __forceinline__ unsigned bfrag_off(int tile, int n, int ks, int c) {
    int nt = n >> 3, nn = n & 7;
    return (unsigned)tile * TILE_B +
           (((ks * 8 + (nt >> 1)) * 32 + (nn * 4 + ((c & 7) >> 1))) * 16) +
           (nt & 1) * 8 + (c >> 3) * 4 + (c & 1) * 2;
}

// ---- prep: B frags fp16(-2c); csq-h2 blob per tile; csq f32; zero scratch ----
__global__ void prep_kernel(const float* __restrict__ codebook) {
    int i = blockIdx.x * blockDim.x + threadIdx.x;
    if (i >= NCODES * DIM) return;
    int k = i >> 6, d = i & 63;
    int tile = k >> 7, n = k & 127;
    *(__half*)(g_cbB + bfrag_off(tile, n, d >> 4, d & 15)) =
        __float2half_rn(-2.0f * codebook[i]);
    g_embed[i] = 0.0f;
    if (d == 0) {
        const float* row = codebook + (size_t)k * DIM;
        float s = 0.0f;
#pragma unroll
        for (int j = 0; j < DIM; j++) s += row[j] * row[j];
        g_csq[k] = s;
        g_counts[k] = 0.0f;
        // csq-h2 blob: u32 index (nt*4 + c4), halves = codes (nt*8+2*c4, +1)
        int nt = n >> 3, c4 = (n & 7) >> 1, half = n & 1;
        *(__half*)(g_cbB + (unsigned)tile * TILE_B + 16384 +
                   ((nt * 4 + c4) * 4) + half * 2) = __float2half_rn(s);
    }
}

// ---- main: 4 warps, m32n128 per warp, 128 pts/CTA ----
__global__ void __launch_bounds__(128, 2) vq_kernel(
    const float* __restrict__ x, const float* __restrict__ codebook,
    float* __restrict__ o_quant, float* __restrict__ o_idx) {
    extern __shared__ char smem[];
    const int tid = threadIdx.x, lane = tid & 31, w = tid >> 5;
    const int r0 = lane >> 2, c4 = lane & 3;

    // A fragments: 2 m-tiles (rows w*32 + mt*16 + r0, +8)
    unsigned afr[2][4][4];
#pragma unroll
    for (int mt = 0; mt < 2; mt++) {
        const float* xr0 = x + ((size_t)blockIdx.x * 128 + w * 32 + mt * 16 + r0) * DIM;
        const float* xr1 = xr0 + 8 * DIM;
#pragma unroll
        for (int ks = 0; ks < 4; ks++) {
            float2 a = *(const float2*)(xr0 + ks * 16 + 2 * c4);
            float2 b = *(const float2*)(xr1 + ks * 16 + 2 * c4);
            float2 c = *(const float2*)(xr0 + ks * 16 + 8 + 2 * c4);
            float2 d = *(const float2*)(xr1 + ks * 16 + 8 + 2 * c4);
            afr[mt][ks][0] = packh2(a.x, a.y);
            afr[mt][ks][1] = packh2(b.x, b.y);
            afr[mt][ks][2] = packh2(c.x, c.y);
            afr[mt][ks][3] = packh2(d.x, d.y);
        }
    }

    const unsigned smem_b = (unsigned)__cvta_generic_to_shared(smem + OFF_B);
#pragma unroll
    for (int t = 0; t < 2; t++) {
        const unsigned char* src = g_cbB + (size_t)t * TILE_B;
        for (int c = tid; c < TILE_B / 16; c += 128)
            cp16(smem_b + t * TILE_B + c * 16, src + c * 16);
        CP_COMMIT();
    }

    unsigned gmin[4] = {0x7BFF7BFFu, 0x7BFF7BFFu, 0x7BFF7BFFu, 0x7BFF7BFFu};
    unsigned* tm = (unsigned*)(smem + OFF_TM);

    for (int t = 0; t < NTIL; ++t) {
        const int buf = t & 1;
        CP_WAIT1();
        __syncthreads();

        const uint4* B4 = (const uint4*)(smem + OFF_B + buf * TILE_B);
        const unsigned* csq2 = (const unsigned*)(smem + OFF_B + buf * TILE_B + 16384);

        unsigned acc[2][32];
#pragma unroll
        for (int ks = 0; ks < 4; ks++)
#pragma unroll
            for (int p = 0; p < 8; p++) {
                uint4 b = B4[(ks * 8 + p) * 32 + lane];
                if (ks == 0) {
#pragma unroll
                    for (int mt = 0; mt < 2; mt++) {
                        mmaZ(acc[mt][(p * 2 + 0) * 2], acc[mt][(p * 2 + 0) * 2 + 1],
                             afr[mt][0], b.x, b.y);
                        mmaZ(acc[mt][(p * 2 + 1) * 2], acc[mt][(p * 2 + 1) * 2 + 1],
                             afr[mt][0], b.z, b.w);
                    }
                } else {
#pragma unroll
                    for (int mt = 0; mt < 2; mt++) {
                        mmaA(acc[mt][(p * 2 + 0) * 2], acc[mt][(p * 2 + 0) * 2 + 1],
                             afr[mt][ks], b.x, b.y);
                        mmaA(acc[mt][(p * 2 + 1) * 2], acc[mt][(p * 2 + 1) * 2 + 1],
                             afr[mt][ks], b.z, b.w);
                    }
                }
            }

        // epilogue: add csq (h2), hmin trees, store subset mins
        unsigned cq[16];
#pragma unroll
        for (int nt = 0; nt < 16; nt++) cq[nt] = csq2[nt * 4 + c4];

#pragma unroll
        for (int mt = 0; mt < 2; mt++) {
#pragma unroll
            for (int slot = 0; slot < 2; slot++) {
                unsigned m[8];
#pragma unroll
                for (int j = 0; j < 8; j++)
                    m[j] = hmin2u(hadd2u(acc[mt][(j + 0) * 2 + slot], cq[j]),
                                  hadd2u(acc[mt][(j + 8) * 2 + slot], cq[j + 8]));
#pragma unroll
                for (int j = 0; j < 4; j++) m[j] = hmin2u(m[j], m[j + 4]);
                unsigned tv = hmin2u(hmin2u(m[0], m[1]), hmin2u(m[2], m[3]));
                gmin[mt * 2 + slot] = hmin2u(gmin[mt * 2 + slot], tv);
                const int pt = w * 32 + mt * 16 + slot * 8 + r0;
                tm[(pt * 33 + t) * 4 + c4] = tv;
            }
        }

        __syncthreads();
        if (t + 2 < NTIL) {
            const unsigned char* src = g_cbB + (size_t)(t + 2) * TILE_B;
            for (int c = tid; c < TILE_B / 16; c += 128)
                cp16(smem_b + buf * TILE_B + c * 16, src + c * 16);
        }
        CP_COMMIT();
    }

    // noisy per-point min
    float* pminS = (float*)(smem + OFF_PMIN);
#pragma unroll
    for (int s = 0; s < 4; s++) {
        unsigned g = gmin[s];
        g = hmin2u(g, __shfl_xor_sync(0xffffffffu, g, 1));
        g = hmin2u(g, __shfl_xor_sync(0xffffffffu, g, 2));
        if (c4 == 0)
            pminS[w * 32 + (s >> 1) * 16 + (s & 1) * 8 + r0] = fminf(h2lo(g), h2hi(g));
    }
    __syncwarp();

    // recovery + exact refine, warp per point (32 points per warp)
    const uint4* tm4 = (const uint4*)tm;
    for (int ii = 0; ii < 32; ii++) {
        const int pl = w * 32 + ii;
        const int gpt = blockIdx.x * 128 + pl;
        const float th = pminS[pl] + MARGIN;

        float2 xv2 = ((const float2*)(x + (size_t)gpt * DIM))[lane];
        float xsq = fmaf(xv2.x, xv2.x, xv2.y * xv2.y);
#pragma unroll
        for (int o = 1; o <= 16; o <<= 1) xsq += __shfl_xor_sync(0xffffffffu, xsq, o);

        uint4 e = tm4[pl * 33 + lane];  // tile = lane, components = c4 0..3
        unsigned m8 = 0;
        if (h2lo(e.x) < th) m8 |= 1u;
        if (h2hi(e.x) < th) m8 |= 2u;
        if (h2lo(e.y) < th) m8 |= 4u;
        if (h2hi(e.y) < th) m8 |= 8u;
        if (h2lo(e.z) < th) m8 |= 16u;
        if (h2hi(e.z) < th) m8 |= 32u;
        if (h2lo(e.w) < th) m8 |= 64u;
        if (h2hi(e.w) < th) m8 |= 128u;

        float bd = 3.4e38f;
        int bi = 0x7FFFFFFF;
        unsigned hitb = __ballot_sync(0xffffffffu, m8 != 0);
        while (hitb) {
            const int src = __ffs(hitb) - 1;
            hitb &= hitb - 1;
            unsigned m = __shfl_sync(0xffffffffu, m8, src);
            for (int bit = 0; bit < 8; bit++) {
                if (!(m & (1u << bit))) continue;
                const int code = src * 128 + (lane >> 1) * 8 + (bit >> 1) * 2 + (bit & 1);
                const int part = lane & 1;
                const float4* xr = (const float4*)(x + (size_t)gpt * DIM) + part * 8;
                const float4* cr = (const float4*)(codebook + (size_t)code * DIM) + part * 8;
                float dot = 0.0f;
#pragma unroll
                for (int j = 0; j < 8; j++) {
                    float4 xa = xr[j], ca = cr[j];
                    dot = fmaf(xa.x, ca.x, dot);
                    dot = fmaf(xa.y, ca.y, dot);
                    dot = fmaf(xa.z, ca.z, dot);
                    dot = fmaf(xa.w, ca.w, dot);
                }
                dot += __shfl_xor_sync(0xffffffffu, dot, 1);
                float dd = fmaf(-2.0f, dot, xsq) + g_csq[code];
                int wi = code;
#pragma unroll
                for (int o = 2; o <= 16; o <<= 1) {
                    float od = __shfl_xor_sync(0xffffffffu, dd, o);
                    int oi = __shfl_xor_sync(0xffffffffu, wi, o);
                    if (od < dd || (od == dd && oi < wi)) { dd = od; wi = oi; }
                }
                if (dd < bd || (dd == bd && wi < bi)) { bd = dd; bi = wi; }
            }
        }

        if (lane == 0) o_idx[gpt] = (float)bi;
        ((float2*)(o_quant + (size_t)gpt * DIM))[lane] =
            ((const float2*)(codebook + (size_t)bi * DIM))[lane];
        if (lane == 0) atomicAdd(&g_counts[bi], 1.0f);
        atomicAdd(&g_embed[(size_t)bi * DIM + 2 * lane], xv2.x);
        atomicAdd(&g_embed[(size_t)bi * DIM + 2 * lane + 1], xv2.y);
    }
}

__global__ void finalize1_kernel(const float* __restrict__ cluster_size,
                                 float* __restrict__ o_cs) {
    __shared__ float warpsum[32];
    __shared__ float s_n;
    float local = 0.0f;
    for (int k = threadIdx.x; k < NCODES; k += blockDim.x) {
        float ncs = DECAY_F * cluster_size[k] + OMD_F * g_counts[k];
        o_cs[k] = ncs;
        g_ncs[k] = ncs;
        local += ncs;
    }
#pragma unroll
    for (int o = 16; o; o >>= 1) local += __shfl_down_sync(0xffffffffu, local, o);
    if ((threadIdx.x & 31) == 0) warpsum[threadIdx.x >> 5] = local;
    __syncthreads();
    if (threadIdx.x < 32) {
        float v = (threadIdx.x < (blockDim.x >> 5)) ? warpsum[threadIdx.x] : 0.0f;
#pragma unroll
        for (int o = 16; o; o >>= 1) v += __shfl_down_sync(0xffffffffu, v, o);
        if (threadIdx.x == 0) s_n = v;
    }
    __syncthreads();
    float n = s_n;
    float denom = n + (float)NCODES * EPS_F;
    for (int k = threadIdx.x; k < NCODES; k += blockDim.x) {
        float sm = (g_ncs[k] + EPS_F) / denom * n;
        g_factor[k] = 1.0f / sm;
    }
}

__global__ void finalize2_kernel(const float* __restrict__ ema_w,
                                 float* __restrict__ o_cb,
                                 float* __restrict__ o_ema) {
    int i = blockIdx.x * blockDim.x + threadIdx.x;
    if (i >= NCODES * DIM) return;
    float e = DECAY_F * ema_w[i] + OMD_F * g_embed[i];
    o_ema[i] = e;
    o_cb[i] = e * g_factor[i >> 6];
}

extern "C" void kernel_launch(void* const* d_in, const int* in_sizes, int n_in,
                              void* d_out, int out_size) {
    const float* x            = (const float*)d_in[0];
    const float* codebook     = (const float*)d_in[1];
    const float* cluster_size = (const float*)d_in[2];
    const float* ema_w        = (const float*)d_in[3];

    float* out     = (float*)d_out;
    float* o_quant = out;
    float* o_idx   = o_quant + (size_t)NPTS * DIM;
    float* o_cb    = o_idx + NPTS;
    float* o_cs    = o_cb + (size_t)NCODES * DIM;
    float* o_ema   = o_cs + NCODES;

    static int smem_set = 0;
    if (!smem_set) {
        cudaFuncSetAttribute(vq_kernel, cudaFuncAttributeMaxDynamicSharedMemorySize, SMEM_TOTAL);
        smem_set = 1;
    }

    prep_kernel<<<(NCODES * DIM + 255) / 256, 256>>>(codebook);
    vq_kernel<<<NPTS / 128, 128, SMEM_TOTAL>>>(x, codebook, o_quant, o_idx);
    finalize1_kernel<<<1, 1024>>>(cluster_size, o_cs);
    finalize2_kernel<<<(NCODES * DIM + 255) / 256, 256>>>(ema_w, o_cb, o_ema);
}